// round 14
// baseline (speedup 1.0000x reference)
#include <cuda_runtime.h>
#include <cuda_bf16.h>
#include <cstdint>

typedef unsigned long long ull;

// ---------------- f32x2 packed helpers (Blackwell) ----------------
__device__ __forceinline__ ull ffma2(ull a, ull b, ull c) {
    ull d;
    asm("fma.rn.f32x2 %0, %1, %2, %3;" : "=l"(d) : "l"(a), "l"(b), "l"(c));
    return d;
}
__device__ __forceinline__ ull pack2(float lo, float hi) {
    ull r;
    asm("mov.b64 %0, {%1, %2};" : "=l"(r) : "f"(lo), "f"(hi));
    return r;
}
__device__ __forceinline__ void unpack2(ull v, float& lo, float& hi) {
    asm("mov.b64 {%0, %1}, %2;" : "=f"(lo), "=f"(hi) : "l"(v));
}
__device__ __forceinline__ ull relu2(ull v) {
    float lo, hi;
    unpack2(v, lo, hi);
    return pack2(fmaxf(lo, 0.0f), fmaxf(hi, 0.0f));
}

static constexpr int C = 16;
static constexpr int TPB = 128;               // 128 threads * 2 rows = 256-row tile
static constexpr int ROWS = 2;                // rows per thread
static constexpr int TILE_ROWS = TPB * ROWS;  // 256
static constexpr int TILE_F4 = TILE_ROWS * 4; // 1024 float4 = 16KB

// Swizzle on float4 index: XOR low 3 bits with bits [4:7).
// Conflict-free for both the coalesced k*TPB+tid pattern and 8*tid+j.
__device__ __forceinline__ int sw(int L) { return L ^ ((L >> 4) & 7); }

// Folded parameters in __constant__ -> weight reads on the constant port.
struct FoldedParams {
    float WcT[C * C];   // [i*16 + o]   Wc^T, o contiguous (pairs adjacent)
    float WbT[C * C];   // [o*16 + q]   Wb^T, q contiguous
    float bc[C];        // folded bias: Wa@bt + ba
    float bb[C];
};

__device__ FoldedParams gStage;
__constant__ __align__(16) FoldedParams cP;

__global__ void fold_kernel(const float* __restrict__ Wt,
                            const float* __restrict__ bt,
                            const float* __restrict__ Wa,
                            const float* __restrict__ ba,
                            const float* __restrict__ Wb,
                            const float* __restrict__ bb)
{
    const int t = threadIdx.x;           // 256 threads
    const int o = t & 15;
    const int i = t >> 4;
    float acc = 0.0f;
#pragma unroll
    for (int m = 0; m < C; m++)
        acc += Wa[o * C + m] * Wt[m * C + i];
    gStage.WcT[i * C + o] = acc;
    gStage.WbT[t] = Wb[(t & 15) * C + (t >> 4)];
    if (t < C) {
        float b = ba[t];
#pragma unroll
        for (int m = 0; m < C; m++)
            b += Wa[t * C + m] * bt[m];
        gStage.bc[t] = b;
        gStage.bb[t] = bb[t];
    }
}

__global__ __launch_bounds__(TPB, 8)
void dmasif_fused_kernel(const float* __restrict__ feat,
                         float* __restrict__ out,
                         long long n)
{
    __shared__ float4 sT[TILE_F4];    // 16KB, features then reused for outputs

    const int tid = threadIdx.x;
    const long long tileBase = (long long)blockIdx.x * TILE_ROWS;
    const bool fullTile = (tileBase + TILE_ROWS <= n);

    if (!fullTile) {
        // ---------- partial-tile path (last block only; dead for N%256==0) ----------
        const long long base = tileBase + (long long)tid * ROWS;
        if (base >= n) return;
        for (int r = 0; r < ROWS; r++) {
            const long long row = base + r;
            if (row >= n) break;
            float h[C];
#pragma unroll
            for (int q = 0; q < C; q++) {
                float a = cP.bc[q];
                for (int i = 0; i < C; i++)
                    a += feat[row * C + i] * cP.WcT[i * C + q];
                h[q] = fmaxf(a, 0.0f);
            }
#pragma unroll
            for (int q = 0; q < C; q++) {
                float a = cP.bb[q];
                for (int o = 0; o < C; o++)
                    a += h[o] * cP.WbT[o * C + q];
                out[row * C + q] = a;
            }
        }
        return;
    }

    // ================= full tile =================
    // 1) coalesced load -> swizzled smem  (8 x float4 per thread)
    {
        const float4* gf4 = reinterpret_cast<const float4*>(feat + tileBase * C);
#pragma unroll
        for (int k = 0; k < 8; k++) {
            const int L = k * TPB + tid;
            sT[sw(L)] = gf4[L];
        }
    }
    __syncthreads();

    // ---- GEMM1 + ReLU: acc[r][p] = (h[r][2p], h[r][2p+1]) ----
    ull acc[ROWS][8];
#pragma unroll
    for (int p = 0; p < 8; p++) {
        const ull bp = *reinterpret_cast<const ull*>(&cP.bc[2 * p]);
#pragma unroll
        for (int r = 0; r < ROWS; r++) acc[r][p] = bp;
    }

#pragma unroll
    for (int ic = 0; ic < 4; ic++) {
        const float4 g0 = sT[sw(8 * tid + 0 * 4 + ic)];
        const float4 g1 = sT[sw(8 * tid + 1 * 4 + ic)];
        float e0v[4] = {g0.x, g0.y, g0.z, g0.w};
        float e1v[4] = {g1.x, g1.y, g1.z, g1.w};
#pragma unroll
        for (int ii = 0; ii < 4; ii++) {
            const int i = ic * 4 + ii;
            const ulonglong2 wA = *reinterpret_cast<const ulonglong2*>(&cP.WcT[i * C + 0]);
            const ulonglong2 wB = *reinterpret_cast<const ulonglong2*>(&cP.WcT[i * C + 4]);
            const ulonglong2 wC = *reinterpret_cast<const ulonglong2*>(&cP.WcT[i * C + 8]);
            const ulonglong2 wD = *reinterpret_cast<const ulonglong2*>(&cP.WcT[i * C + 12]);
            const ull d0 = pack2(e0v[ii], e0v[ii]);
            const ull d1 = pack2(e1v[ii], e1v[ii]);
            acc[0][0] = ffma2(d0, wA.x, acc[0][0]); acc[0][1] = ffma2(d0, wA.y, acc[0][1]);
            acc[0][2] = ffma2(d0, wB.x, acc[0][2]); acc[0][3] = ffma2(d0, wB.y, acc[0][3]);
            acc[0][4] = ffma2(d0, wC.x, acc[0][4]); acc[0][5] = ffma2(d0, wC.y, acc[0][5]);
            acc[0][6] = ffma2(d0, wD.x, acc[0][6]); acc[0][7] = ffma2(d0, wD.y, acc[0][7]);
            acc[1][0] = ffma2(d1, wA.x, acc[1][0]); acc[1][1] = ffma2(d1, wA.y, acc[1][1]);
            acc[1][2] = ffma2(d1, wB.x, acc[1][2]); acc[1][3] = ffma2(d1, wB.y, acc[1][3]);
            acc[1][4] = ffma2(d1, wC.x, acc[1][4]); acc[1][5] = ffma2(d1, wC.y, acc[1][5]);
            acc[1][6] = ffma2(d1, wD.x, acc[1][6]); acc[1][7] = ffma2(d1, wD.y, acc[1][7]);
        }
    }

#pragma unroll
    for (int r = 0; r < ROWS; r++)
#pragma unroll
        for (int p = 0; p < 8; p++) acc[r][p] = relu2(acc[r][p]);

    // ---- GEMM2 in QUARTERS (4 q-values = 2 pairs live at a time) to keep
    // the live-register peak low enough for 8 CTAs/SM (64 regs). ----
#pragma unroll
    for (int qt = 0; qt < 4; qt++) {
        ull a2[ROWS][2];
        {
            const ull bp0 = *reinterpret_cast<const ull*>(&cP.bb[4 * qt + 0]);
            const ull bp1 = *reinterpret_cast<const ull*>(&cP.bb[4 * qt + 2]);
#pragma unroll
            for (int r = 0; r < ROWS; r++) { a2[r][0] = bp0; a2[r][1] = bp1; }
        }
#pragma unroll
        for (int o = 0; o < C; o++) {
            // one LDC.128: 4 q-weights (2 pairs) for this o, this quarter
            const ulonglong2 w = *reinterpret_cast<const ulonglong2*>(&cP.WbT[o * C + 4 * qt]);
#pragma unroll
            for (int r = 0; r < ROWS; r++) {
                float hlo, hhi;
                unpack2(acc[r][o >> 1], hlo, hhi);
                const float hs = (o & 1) ? hhi : hlo;
                const ull hd = pack2(hs, hs);
                a2[r][0] = ffma2(hd, w.x, a2[r][0]);
                a2[r][1] = ffma2(hd, w.y, a2[r][1]);
            }
        }
#pragma unroll
        for (int r = 0; r < ROWS; r++) {
            float v0, v1, v2, v3;
            unpack2(a2[r][0], v0, v1);
            unpack2(a2[r][1], v2, v3);
            sT[sw(8 * tid + r * 4 + qt)] = make_float4(v0, v1, v2, v3);
        }
    }
    __syncthreads();

    // 3) coalesced store from swizzled smem
    {
        float4* go4 = reinterpret_cast<float4*>(out + tileBase * C);
#pragma unroll
        for (int k = 0; k < 8; k++) {
            const int L = k * TPB + tid;
            go4[L] = sT[sw(L)];
        }
    }
}

extern "C" void kernel_launch(void* const* d_in, const int* in_sizes, int n_in,
                              void* d_out, int out_size)
{
    // metadata order: features, points, nuv, Wt, bt, Wa, ba, Wb, bb, ranges
    const float* feat = (const float*)d_in[0];
    const float* Wt   = (const float*)d_in[3];
    const float* bt   = (const float*)d_in[4];
    const float* Wa   = (const float*)d_in[5];
    const float* ba   = (const float*)d_in[6];
    const float* Wb   = (const float*)d_in[7];
    const float* bb   = (const float*)d_in[8];
    float* out = (float*)d_out;

    const long long n = (long long)in_sizes[0] / C;
    const int blocks = (int)((n + TILE_ROWS - 1) / TILE_ROWS);

    fold_kernel<<<1, 256>>>(Wt, bt, Wa, ba, Wb, bb);

    void* stage_ptr = nullptr;
    cudaGetSymbolAddress(&stage_ptr, gStage);
    cudaMemcpyToSymbolAsync(cP, stage_ptr, sizeof(FoldedParams), 0,
                            cudaMemcpyDeviceToDevice, 0);

    dmasif_fused_kernel<<<blocks, TPB>>>(feat, out, n);
}